// round 7
// baseline (speedup 1.0000x reference)
#include <cuda_runtime.h>

#define BATCH 16
#define NPTS 4096
#define NPT 1024
#define KNB 32
#define R2C 0.04f

// ---------------- scratch (device globals; no allocation allowed) ----------
__device__ float g_P1[BATCH * NPTS * 64];     // points @ w0[:64] + b0
__device__ float g_xyzT[BATCH * 3 * NPTS];    // xyz transposed per batch
__device__ int   g_ball[BATCH * NPT * KNB];   // ball-query indices

// ---------------- kernel 1: combined FPS + P1 + transpose ------------------
// blocks 0..15   : farthest point sampling (one block per batch, serial)
// blocks 16..143 : P1 = points @ w0[:64] + b0 (512 rows per block)
// blocks 144..271: xyz AoS->SoA transpose
// The fps blocks run ~300us on 16 SMs; p1/transpose fill the other SMs and
// finish long before fps does, so their cost vanishes.
__global__ __launch_bounds__(512) void pre_kernel(
    const float* __restrict__ xyz, const float* __restrict__ points,
    const float* __restrict__ w0, const float* __restrict__ b0,
    float* __restrict__ newxyz) {
    extern __shared__ float sm[];
    int bid = blockIdx.x;
    int tid = threadIdx.x;

    if (bid < 16) {
        // ---------------- FPS ----------------
        float* shx = sm;
        float* shy = sm + NPTS;
        float* shz = sm + 2 * NPTS;
        float* wv  = sm + 3 * NPTS;          // [2][16] double-buffered partial vals
        int*   wi  = (int*)(sm + 3 * NPTS + 32);  // [2][16] partial idx

        int b = bid;
        const float* xb = xyz + (size_t)b * NPTS * 3;
        for (int i = tid; i < NPTS; i += 512) {
            shx[i] = xb[i * 3 + 0];
            shy[i] = xb[i * 3 + 1];
            shz[i] = xb[i * 3 + 2];
        }
        __syncthreads();

        float lx[8], ly[8], lz[8], ld[8];
#pragma unroll
        for (int j = 0; j < 8; j++) {
            int p = tid + j * 512;
            lx[j] = shx[p]; ly[j] = shy[p]; lz[j] = shz[p];
            ld[j] = 1e10f;
        }

        int lane = tid & 31, warp = tid >> 5;
        int far = 0;
        float* outb = newxyz + (size_t)b * NPT * 3;
#pragma unroll 1
        for (int it = 0; it < NPT; it++) {
            int par = it & 1;
            float cx = shx[far], cy = shy[far], cz = shz[far];
            if (tid == 0) {
                outb[it * 3 + 0] = cx;
                outb[it * 3 + 1] = cy;
                outb[it * 3 + 2] = cz;
            }
            // two independent compare chains (shorter dependency), chain0 has
            // strictly lower indices than chain1 so tie-break stays lowest-idx
            float bv0 = -1.0f, bv1 = -1.0f; int bi0 = 0, bi1 = 0;
#pragma unroll
            for (int j = 0; j < 4; j++) {
                int p = tid + j * 512;
                float dx = lx[j] - cx, dy = ly[j] - cy, dz = lz[j] - cz;
                float nd = fminf(ld[j], dx * dx + dy * dy + dz * dz);
                ld[j] = nd;
                if (nd > bv0) { bv0 = nd; bi0 = p; }
            }
#pragma unroll
            for (int j = 4; j < 8; j++) {
                int p = tid + j * 512;
                float dx = lx[j] - cx, dy = ly[j] - cy, dz = lz[j] - cz;
                float nd = fminf(ld[j], dx * dx + dy * dy + dz * dz);
                ld[j] = nd;
                if (nd > bv1) { bv1 = nd; bi1 = p; }
            }
            float bv = bv0; int bi = bi0;
            if (bv1 > bv0) { bv = bv1; bi = bi1; }
#pragma unroll
            for (int off = 16; off > 0; off >>= 1) {
                float ov = __shfl_down_sync(0xffffffffu, bv, off);
                int   oi = __shfl_down_sync(0xffffffffu, bi, off);
                if (ov > bv || (ov == bv && oi < bi)) { bv = ov; bi = oi; }
            }
            if (lane == 0) { wv[par * 16 + warp] = bv; wi[par * 16 + warp] = bi; }
            __syncthreads();
            // every warp redundantly reduces the 16 partials -> no second bar
            bv = (lane < 16) ? wv[par * 16 + lane] : -2.0f;
            bi = (lane < 16) ? wi[par * 16 + lane] : 0x7fffffff;
#pragma unroll
            for (int off = 8; off > 0; off >>= 1) {
                float ov = __shfl_down_sync(0xffffffffu, bv, off);
                int   oi = __shfl_down_sync(0xffffffffu, bi, off);
                if (ov > bv || (ov == bv && oi < bi)) { bv = ov; bi = oi; }
            }
            far = __shfl_sync(0xffffffffu, bi, 0);
        }
    } else if (bid < 144) {
        // ---------------- P1 GEMM ----------------
        float* sw = sm;            // 4096
        float* sb = sm + 4096;     // 64
        for (int i = tid; i < 4096; i += 512) sw[i] = w0[i];
        if (tid < 64) sb[tid] = b0[tid];
        __syncthreads();

        int row = (bid - 16) * 512 + tid;          // b*4096 + n
        const float* x = points + (size_t)row * 64;
        float acc[64];
#pragma unroll
        for (int f = 0; f < 64; f++) acc[f] = sb[f];
#pragma unroll 2
        for (int c4 = 0; c4 < 16; c4++) {
            float4 xv = *(const float4*)(x + c4 * 4);
            float xs[4] = {xv.x, xv.y, xv.z, xv.w};
#pragma unroll
            for (int u = 0; u < 4; u++) {
                int c = c4 * 4 + u;
#pragma unroll
                for (int f4 = 0; f4 < 16; f4++) {
                    float4 wvv = *(const float4*)&sw[c * 64 + f4 * 4];
                    acc[f4 * 4 + 0] += xs[u] * wvv.x;
                    acc[f4 * 4 + 1] += xs[u] * wvv.y;
                    acc[f4 * 4 + 2] += xs[u] * wvv.z;
                    acc[f4 * 4 + 3] += xs[u] * wvv.w;
                }
            }
        }
        float* o = g_P1 + (size_t)row * 64;
#pragma unroll
        for (int f4 = 0; f4 < 16; f4++)
            *(float4*)(o + f4 * 4) = make_float4(acc[f4 * 4 + 0], acc[f4 * 4 + 1],
                                                 acc[f4 * 4 + 2], acc[f4 * 4 + 3]);
    } else {
        // ---------------- transpose xyz ----------------
        int i = (bid - 144) * 512 + tid;
        int b = i / NPTS, n = i % NPTS;
        float x = xyz[(size_t)i * 3 + 0];
        float y = xyz[(size_t)i * 3 + 1];
        float z = xyz[(size_t)i * 3 + 2];
        g_xyzT[b * 3 * NPTS + 0 * NPTS + n] = x;
        g_xyzT[b * 3 * NPTS + 1 * NPTS + n] = y;
        g_xyzT[b * 3 * NPTS + 2 * NPTS + n] = z;
    }
}

// ---------------- kernel 2: ball query, shared-staged ----------------------
// 8 centroids (warps) per block, all in the same batch (1024 % 8 == 0).
// The batch's SoA xyz (48KB) is staged in shared once per block.
__global__ __launch_bounds__(256) void query_kernel(const float* __restrict__ newxyz) {
    extern __shared__ float s[];      // 3 * 4096
    int tid = threadIdx.x;
    int b = blockIdx.x >> 7;          // 128 blocks per batch
    const float4* src = (const float4*)(g_xyzT + (size_t)b * 3 * NPTS);
    float4* dst = (float4*)s;
#pragma unroll
    for (int i = tid; i < 3 * NPTS / 4; i += 256) dst[i] = src[i];
    __syncthreads();

    int warp = tid >> 5, lane = tid & 31;
    int cid = blockIdx.x * 8 + warp;
    float cx = newxyz[(size_t)cid * 3 + 0];
    float cy = newxyz[(size_t)cid * 3 + 1];
    float cz = newxyz[(size_t)cid * 3 + 2];
    const float* sx = s;
    const float* sy = s + NPTS;
    const float* sz = s + 2 * NPTS;
    int* outp = g_ball + (size_t)cid * KNB;

    int cnt = 0, first = 0;
    bool havefirst = false;
    for (int ch = 0; ch < NPTS / 32; ch++) {
        int n = ch * 32 + lane;
        float dx = sx[n] - cx, dy = sy[n] - cy, dz = sz[n] - cz;
        float d2 = dx * dx + dy * dy + dz * dz;
        unsigned m = __ballot_sync(0xffffffffu, d2 <= R2C);
        if (m) {
            if (!havefirst) { first = ch * 32 + __ffs(m) - 1; havefirst = true; }
            int pos = cnt + __popc(m & ((1u << lane) - 1u));
            if (((m >> lane) & 1u) && pos < KNB) outp[pos] = n;
            cnt += __popc(m);
            if (cnt >= KNB) break;   // cnt warp-uniform
        }
    }
    if (cnt < KNB && lane >= cnt) outp[lane] = first;   // pad with first match
}

// ---------------- kernel 3: fused grouping + MLP + maxpool -----------------
// Block = 256 threads = 2 groups x 128; each group processes 2 centroids.
// smem 67KB -> 3 CTAs/SM. Max-pool over k via width-8 shfl (no smem, no bars).
__global__ __launch_bounds__(256, 3) void mlp_kernel(
    const float* __restrict__ xyz, const float* __restrict__ w0,
    const float* __restrict__ b1, const float* __restrict__ w1,
    const float* __restrict__ w2, const float* __restrict__ b2,
    const float* __restrict__ newxyz, float* __restrict__ newpts) {
    extern __shared__ char smraw[];
    float* w1s  = (float*)smraw;            // 4096
    float* w2s  = w1s + 4096;               // 8192
    float* w0t  = w2s + 8192;               // 192 (xyz rows of w0)
    float* b1s  = w0t + 192;                // 64
    float* b2s  = b1s + 64;                 // 128
    float* hbuf = b2s + 128;                // 2 * 2048

    int tid = threadIdx.x;
    for (int i = tid; i < 4096; i += 256) w1s[i] = w1[i];
    for (int i = tid; i < 8192; i += 256) w2s[i] = w2[i];
    if (tid < 192) w0t[tid] = w0[4096 + tid];   // rows 64..66 of [67,64]
    if (tid < 64)  b1s[tid] = b1[tid];
    if (tid < 128) b2s[tid] = b2[tid];
    __syncthreads();

    int g  = tid >> 7;
    int gt = tid & 127;
    float* hb = hbuf + g * 2048;
    int kt = gt & 7, ft = gt >> 3;
    int k0 = kt * 4, f0 = ft * 4, f2 = ft * 8;

    for (int itc = 0; itc < 2; itc++) {
        int cid = blockIdx.x * 4 + g * 2 + itc;
        int b = cid >> 10;

        // layer 0 (redundant gather per thread, no staging barrier):
        // relu(P1[idx] + dxyz @ w0[64:67]) -> hb transposed [f][k]
        float c0 = newxyz[(size_t)cid * 3 + 0];
        float c1 = newxyz[(size_t)cid * 3 + 1];
        float c2 = newxyz[(size_t)cid * 3 + 2];
#pragma unroll
        for (int kk = 0; kk < 4; kk++) {
            int k = k0 + kk;
            int pi = g_ball[(size_t)cid * 32 + k];
            const float* pp = xyz + ((size_t)b * NPTS + pi) * 3;
            float dx = pp[0] - c0, dy = pp[1] - c1, dz = pp[2] - c2;
            const float4 p = *(const float4*)(g_P1 + ((size_t)b * NPTS + pi) * 64 + f0);
            float v;
            v = p.x + dx * w0t[f0 + 0] + dy * w0t[64 + f0 + 0] + dz * w0t[128 + f0 + 0];
            hb[(f0 + 0) * 32 + k] = fmaxf(v, 0.f);
            v = p.y + dx * w0t[f0 + 1] + dy * w0t[64 + f0 + 1] + dz * w0t[128 + f0 + 1];
            hb[(f0 + 1) * 32 + k] = fmaxf(v, 0.f);
            v = p.z + dx * w0t[f0 + 2] + dy * w0t[64 + f0 + 2] + dz * w0t[128 + f0 + 2];
            hb[(f0 + 2) * 32 + k] = fmaxf(v, 0.f);
            v = p.w + dx * w0t[f0 + 3] + dy * w0t[64 + f0 + 3] + dz * w0t[128 + f0 + 3];
            hb[(f0 + 3) * 32 + k] = fmaxf(v, 0.f);
        }
        __syncthreads();

        // layer 1: h1 = relu(h0 @ w1 + b1), 4k x 4f register tile
        float a[4][4];
#pragma unroll
        for (int j = 0; j < 4; j++) {
            float bb = b1s[f0 + j];
            a[0][j] = bb; a[1][j] = bb; a[2][j] = bb; a[3][j] = bb;
        }
#pragma unroll 8
        for (int c = 0; c < 64; c++) {
            float4 hv = *(const float4*)&hb[c * 32 + k0];
            float4 wv = *(const float4*)&w1s[c * 64 + f0];
            a[0][0] += hv.x * wv.x; a[0][1] += hv.x * wv.y; a[0][2] += hv.x * wv.z; a[0][3] += hv.x * wv.w;
            a[1][0] += hv.y * wv.x; a[1][1] += hv.y * wv.y; a[1][2] += hv.y * wv.z; a[1][3] += hv.y * wv.w;
            a[2][0] += hv.z * wv.x; a[2][1] += hv.z * wv.y; a[2][2] += hv.z * wv.z; a[2][3] += hv.z * wv.w;
            a[3][0] += hv.w * wv.x; a[3][1] += hv.w * wv.y; a[3][2] += hv.w * wv.z; a[3][3] += hv.w * wv.w;
        }
        __syncthreads();   // all reads of h0 done before overwrite
#pragma unroll
        for (int j = 0; j < 4; j++) {
            float4 o = make_float4(fmaxf(a[0][j], 0.f), fmaxf(a[1][j], 0.f),
                                   fmaxf(a[2][j], 0.f), fmaxf(a[3][j], 0.f));
            *(float4*)&hb[(f0 + j) * 32 + k0] = o;
        }
        __syncthreads();

        // layer 2: 4k x 8f register tile
        float a2[4][8];
#pragma unroll
        for (int k = 0; k < 4; k++)
#pragma unroll
            for (int j = 0; j < 8; j++) a2[k][j] = 0.f;
#pragma unroll 4
        for (int c = 0; c < 64; c++) {
            float4 hv = *(const float4*)&hb[c * 32 + k0];
            float4 wa = *(const float4*)&w2s[c * 128 + f2];
            float4 wb = *(const float4*)&w2s[c * 128 + f2 + 4];
            float hvv[4] = {hv.x, hv.y, hv.z, hv.w};
            float wvv[8] = {wa.x, wa.y, wa.z, wa.w, wb.x, wb.y, wb.z, wb.w};
#pragma unroll
            for (int k = 0; k < 4; k++)
#pragma unroll
                for (int j = 0; j < 8; j++) a2[k][j] += hvv[k] * wvv[j];
        }

        // bias + relu + max over local 4 k, then max over the 8 kt lanes
        // (consecutive lanes, same ft) via width-8 shfl tree. Exact.
        float m[8];
#pragma unroll
        for (int j = 0; j < 8; j++) {
            float bb = b2s[f2 + j];
            float v = fmaxf(a2[0][j] + bb, 0.f);
            v = fmaxf(v, fmaxf(a2[1][j] + bb, 0.f));
            v = fmaxf(v, fmaxf(a2[2][j] + bb, 0.f));
            v = fmaxf(v, fmaxf(a2[3][j] + bb, 0.f));
            m[j] = v;
        }
#pragma unroll
        for (int off = 4; off > 0; off >>= 1)
#pragma unroll
            for (int j = 0; j < 8; j++)
                m[j] = fmaxf(m[j], __shfl_down_sync(0xffffffffu, m[j], off, 8));
        if (kt == 0) {
            float* op = newpts + (size_t)cid * 128 + f2;
            *(float4*)op       = make_float4(m[0], m[1], m[2], m[3]);
            *(float4*)(op + 4) = make_float4(m[4], m[5], m[6], m[7]);
        }
        __syncthreads();   // protect hb reuse next iteration
    }
}

// ---------------- launch ----------------------------------------------------
extern "C" void kernel_launch(void* const* d_in, const int* in_sizes, int n_in,
                              void* d_out, int out_size) {
    const float* xyz    = (const float*)d_in[0];
    const float* points = (const float*)d_in[1];
    const float* w0     = (const float*)d_in[2];
    const float* b0     = (const float*)d_in[3];
    const float* w1     = (const float*)d_in[4];
    const float* b1     = (const float*)d_in[5];
    const float* w2     = (const float*)d_in[6];
    const float* b2     = (const float*)d_in[7];

    float* newxyz = (float*)d_out;                       // [16,1024,3]
    float* newpts = newxyz + (size_t)BATCH * NPT * 3;    // [16,1024,128]

    cudaFuncSetAttribute(pre_kernel,   cudaFuncAttributeMaxDynamicSharedMemorySize, 49408);
    cudaFuncSetAttribute(query_kernel, cudaFuncAttributeMaxDynamicSharedMemorySize, 49152);
    cudaFuncSetAttribute(mlp_kernel,   cudaFuncAttributeMaxDynamicSharedMemorySize, 67072);

    pre_kernel<<<272, 512, 49408>>>(xyz, points, w0, b0, newxyz);
    query_kernel<<<BATCH * NPT / 8, 256, 49152>>>(newxyz);
    mlp_kernel<<<BATCH * NPT / 4, 256, 67072>>>(xyz, w0, b1, w1, w2, b2, newxyz, newpts);
}

// round 11
// speedup vs baseline: 1.9240x; 1.9240x over previous
#include <cuda_runtime.h>

#define BATCH 16
#define NPTS 4096
#define NPT 1024
#define KNB 32
#define R2C 0.04f

// ---------------- scratch (device globals; no allocation allowed) ----------
__device__ float g_P1[BATCH * NPTS * 64];     // points @ w0[:64] + b0
__device__ float g_xyzT[BATCH * 3 * NPTS];    // xyz transposed per batch
__device__ int   g_ball[BATCH * NPT * KNB];   // ball-query indices

// ---------------- kernel 1: combined FPS + P1 + transpose ------------------
// blocks 0..15   : farthest point sampling (one block per batch, serial)
// blocks 16..143 : P1 = points @ w0[:64] + b0 (512 rows per block)
// blocks 144..271: xyz AoS->SoA transpose
// FPS is ISSUE-bound (ncu: issue=55%, all mem ~0) -> minimize instructions
// per iteration. Value-only argmax in the hot loop; index recovered by an
// exact-equality rescan + shared atomicMin. Float dist >= 0 so its bit
// pattern is order-monotonic -> cross-warp value max via shared atomicMax
// on the bits (replaces a whole reduce stage with 16 single-lane atomics).
__global__ __launch_bounds__(512) void pre_kernel(
    const float* __restrict__ xyz, const float* __restrict__ points,
    const float* __restrict__ w0, const float* __restrict__ b0,
    float* __restrict__ newxyz) {
    extern __shared__ float sm[];
    int bid = blockIdx.x;
    int tid = threadIdx.x;

    if (bid < 16) {
        // ---------------- FPS ----------------
        float* shx = sm;
        float* shy = sm + NPTS;
        float* shz = sm + 2 * NPTS;
        unsigned* gbits = (unsigned*)(sm + 3 * NPTS);   // [2] max dist bits
        int*      sfar  = (int*)(sm + 3 * NPTS + 2);    // [2] argmax index

        int b = bid;
        const float* xb = xyz + (size_t)b * NPTS * 3;
        for (int i = tid; i < NPTS; i += 512) {
            shx[i] = xb[i * 3 + 0];
            shy[i] = xb[i * 3 + 1];
            shz[i] = xb[i * 3 + 2];
        }
        if (tid < 2) { gbits[tid] = 0u; sfar[tid] = 0x7fffffff; }
        __syncthreads();

        float lx[8], ly[8], lz[8], ld[8];
#pragma unroll
        for (int j = 0; j < 8; j++) {
            int p = tid + j * 512;
            lx[j] = shx[p]; ly[j] = shy[p]; lz[j] = shz[p];
            ld[j] = 1e10f;
        }

        int lane = tid & 31;
        int far = 0;
        float* outb = newxyz + (size_t)b * NPT * 3;
#pragma unroll 1
        for (int it = 0; it < NPT; it++) {
            int par = it & 1;
            float cx = shx[far], cy = shy[far], cz = shz[far];
            if (tid == 0) {
                outb[it * 3 + 0] = cx;
                outb[it * 3 + 1] = cy;
                outb[it * 3 + 2] = cz;
            }
            // phase 1: update dists, track VALUE max only (8 instr/point)
            float bv = -1.0f;
#pragma unroll
            for (int j = 0; j < 8; j++) {
                float dx = lx[j] - cx, dy = ly[j] - cy, dz = lz[j] - cz;
                float nd = fminf(ld[j], dx * dx + dy * dy + dz * dz);
                ld[j] = nd;
                bv = fmaxf(bv, nd);
            }
            // phase 2: warp value-max, lane0 publishes via bit-atomicMax
#pragma unroll
            for (int off = 16; off > 0; off >>= 1)
                bv = fmaxf(bv, __shfl_down_sync(0xffffffffu, bv, off));
            if (lane == 0) atomicMax(&gbits[par], __float_as_uint(bv));
            __syncthreads();   // bar1: all value atomics done

            // phase 3: exact-equality rescan -> lowest matching index
            float gmax = __uint_as_float(gbits[par]);
            int cand = 0x7fffffff;
#pragma unroll
            for (int j = 0; j < 8; j++)
                if (ld[j] == gmax) cand = min(cand, tid + j * 512);
            if (cand != 0x7fffffff) atomicMin(&sfar[par], cand);
            // reset the OTHER parity slot inside the (bar1, bar2) window:
            // its last readers finished before bar1, next writers start
            // after bar2 -> race-free.
            if (tid == 0) { gbits[par ^ 1] = 0u; sfar[par ^ 1] = 0x7fffffff; }
            __syncthreads();   // bar2: all index atomics done
            far = sfar[par];
        }
    } else if (bid < 144) {
        // ---------------- P1 GEMM ----------------
        float* sw = sm;            // 4096
        float* sb = sm + 4096;     // 64
        for (int i = tid; i < 4096; i += 512) sw[i] = w0[i];
        if (tid < 64) sb[tid] = b0[tid];
        __syncthreads();

        int row = (bid - 16) * 512 + tid;          // b*4096 + n
        const float* x = points + (size_t)row * 64;
        float acc[64];
#pragma unroll
        for (int f = 0; f < 64; f++) acc[f] = sb[f];
#pragma unroll 2
        for (int c4 = 0; c4 < 16; c4++) {
            float4 xv = *(const float4*)(x + c4 * 4);
            float xs[4] = {xv.x, xv.y, xv.z, xv.w};
#pragma unroll
            for (int u = 0; u < 4; u++) {
                int c = c4 * 4 + u;
#pragma unroll
                for (int f4 = 0; f4 < 16; f4++) {
                    float4 wvv = *(const float4*)&sw[c * 64 + f4 * 4];
                    acc[f4 * 4 + 0] += xs[u] * wvv.x;
                    acc[f4 * 4 + 1] += xs[u] * wvv.y;
                    acc[f4 * 4 + 2] += xs[u] * wvv.z;
                    acc[f4 * 4 + 3] += xs[u] * wvv.w;
                }
            }
        }
        float* o = g_P1 + (size_t)row * 64;
#pragma unroll
        for (int f4 = 0; f4 < 16; f4++)
            *(float4*)(o + f4 * 4) = make_float4(acc[f4 * 4 + 0], acc[f4 * 4 + 1],
                                                 acc[f4 * 4 + 2], acc[f4 * 4 + 3]);
    } else {
        // ---------------- transpose xyz ----------------
        int i = (bid - 144) * 512 + tid;
        int b = i / NPTS, n = i % NPTS;
        float x = xyz[(size_t)i * 3 + 0];
        float y = xyz[(size_t)i * 3 + 1];
        float z = xyz[(size_t)i * 3 + 2];
        g_xyzT[b * 3 * NPTS + 0 * NPTS + n] = x;
        g_xyzT[b * 3 * NPTS + 1 * NPTS + n] = y;
        g_xyzT[b * 3 * NPTS + 2 * NPTS + n] = z;
    }
}

// ---------------- kernel 2: ball query, shared-staged ----------------------
// 8 centroids (warps) per block, all in the same batch (1024 % 8 == 0).
// The batch's SoA xyz (48KB) is staged in shared once per block.
__global__ __launch_bounds__(256) void query_kernel(const float* __restrict__ newxyz) {
    extern __shared__ float s[];      // 3 * 4096
    int tid = threadIdx.x;
    int b = blockIdx.x >> 7;          // 128 blocks per batch
    const float4* src = (const float4*)(g_xyzT + (size_t)b * 3 * NPTS);
    float4* dst = (float4*)s;
#pragma unroll
    for (int i = tid; i < 3 * NPTS / 4; i += 256) dst[i] = src[i];
    __syncthreads();

    int warp = tid >> 5, lane = tid & 31;
    int cid = blockIdx.x * 8 + warp;
    float cx = newxyz[(size_t)cid * 3 + 0];
    float cy = newxyz[(size_t)cid * 3 + 1];
    float cz = newxyz[(size_t)cid * 3 + 2];
    const float* sx = s;
    const float* sy = s + NPTS;
    const float* sz = s + 2 * NPTS;
    int* outp = g_ball + (size_t)cid * KNB;

    int cnt = 0, first = 0;
    bool havefirst = false;
    for (int ch = 0; ch < NPTS / 32; ch++) {
        int n = ch * 32 + lane;
        float dx = sx[n] - cx, dy = sy[n] - cy, dz = sz[n] - cz;
        float d2 = dx * dx + dy * dy + dz * dz;
        unsigned m = __ballot_sync(0xffffffffu, d2 <= R2C);
        if (m) {
            if (!havefirst) { first = ch * 32 + __ffs(m) - 1; havefirst = true; }
            int pos = cnt + __popc(m & ((1u << lane) - 1u));
            if (((m >> lane) & 1u) && pos < KNB) outp[pos] = n;
            cnt += __popc(m);
            if (cnt >= KNB) break;   // cnt warp-uniform
        }
    }
    if (cnt < KNB && lane >= cnt) outp[lane] = first;   // pad with first match
}

// ---------------- kernel 3: fused grouping + MLP + maxpool -----------------
// Block = 256 threads = 2 groups x 128; each group processes 2 centroids.
// smem 67KB -> 3 CTAs/SM. Max-pool over k via width-8 shfl (no smem, no bars).
__global__ __launch_bounds__(256, 3) void mlp_kernel(
    const float* __restrict__ xyz, const float* __restrict__ w0,
    const float* __restrict__ b1, const float* __restrict__ w1,
    const float* __restrict__ w2, const float* __restrict__ b2,
    const float* __restrict__ newxyz, float* __restrict__ newpts) {
    extern __shared__ char smraw[];
    float* w1s  = (float*)smraw;            // 4096
    float* w2s  = w1s + 4096;               // 8192
    float* w0t  = w2s + 8192;               // 192 (xyz rows of w0)
    float* b1s  = w0t + 192;                // 64
    float* b2s  = b1s + 64;                 // 128
    float* hbuf = b2s + 128;                // 2 * 2048

    int tid = threadIdx.x;
    for (int i = tid; i < 4096; i += 256) w1s[i] = w1[i];
    for (int i = tid; i < 8192; i += 256) w2s[i] = w2[i];
    if (tid < 192) w0t[tid] = w0[4096 + tid];   // rows 64..66 of [67,64]
    if (tid < 64)  b1s[tid] = b1[tid];
    if (tid < 128) b2s[tid] = b2[tid];
    __syncthreads();

    int g  = tid >> 7;
    int gt = tid & 127;
    float* hb = hbuf + g * 2048;
    int kt = gt & 7, ft = gt >> 3;
    int k0 = kt * 4, f0 = ft * 4, f2 = ft * 8;

    for (int itc = 0; itc < 2; itc++) {
        int cid = blockIdx.x * 4 + g * 2 + itc;
        int b = cid >> 10;

        // layer 0 (redundant gather per thread, no staging barrier):
        // relu(P1[idx] + dxyz @ w0[64:67]) -> hb transposed [f][k]
        float c0 = newxyz[(size_t)cid * 3 + 0];
        float c1 = newxyz[(size_t)cid * 3 + 1];
        float c2 = newxyz[(size_t)cid * 3 + 2];
#pragma unroll
        for (int kk = 0; kk < 4; kk++) {
            int k = k0 + kk;
            int pi = g_ball[(size_t)cid * 32 + k];
            const float* pp = xyz + ((size_t)b * NPTS + pi) * 3;
            float dx = pp[0] - c0, dy = pp[1] - c1, dz = pp[2] - c2;
            const float4 p = *(const float4*)(g_P1 + ((size_t)b * NPTS + pi) * 64 + f0);
            float v;
            v = p.x + dx * w0t[f0 + 0] + dy * w0t[64 + f0 + 0] + dz * w0t[128 + f0 + 0];
            hb[(f0 + 0) * 32 + k] = fmaxf(v, 0.f);
            v = p.y + dx * w0t[f0 + 1] + dy * w0t[64 + f0 + 1] + dz * w0t[128 + f0 + 1];
            hb[(f0 + 1) * 32 + k] = fmaxf(v, 0.f);
            v = p.z + dx * w0t[f0 + 2] + dy * w0t[64 + f0 + 2] + dz * w0t[128 + f0 + 2];
            hb[(f0 + 2) * 32 + k] = fmaxf(v, 0.f);
            v = p.w + dx * w0t[f0 + 3] + dy * w0t[64 + f0 + 3] + dz * w0t[128 + f0 + 3];
            hb[(f0 + 3) * 32 + k] = fmaxf(v, 0.f);
        }
        __syncthreads();

        // layer 1: h1 = relu(h0 @ w1 + b1), 4k x 4f register tile
        float a[4][4];
#pragma unroll
        for (int j = 0; j < 4; j++) {
            float bb = b1s[f0 + j];
            a[0][j] = bb; a[1][j] = bb; a[2][j] = bb; a[3][j] = bb;
        }
#pragma unroll 8
        for (int c = 0; c < 64; c++) {
            float4 hv = *(const float4*)&hb[c * 32 + k0];
            float4 wv = *(const float4*)&w1s[c * 64 + f0];
            a[0][0] += hv.x * wv.x; a[0][1] += hv.x * wv.y; a[0][2] += hv.x * wv.z; a[0][3] += hv.x * wv.w;
            a[1][0] += hv.y * wv.x; a[1][1] += hv.y * wv.y; a[1][2] += hv.y * wv.z; a[1][3] += hv.y * wv.w;
            a[2][0] += hv.z * wv.x; a[2][1] += hv.z * wv.y; a[2][2] += hv.z * wv.z; a[2][3] += hv.z * wv.w;
            a[3][0] += hv.w * wv.x; a[3][1] += hv.w * wv.y; a[3][2] += hv.w * wv.z; a[3][3] += hv.w * wv.w;
        }
        __syncthreads();   // all reads of h0 done before overwrite
#pragma unroll
        for (int j = 0; j < 4; j++) {
            float4 o = make_float4(fmaxf(a[0][j], 0.f), fmaxf(a[1][j], 0.f),
                                   fmaxf(a[2][j], 0.f), fmaxf(a[3][j], 0.f));
            *(float4*)&hb[(f0 + j) * 32 + k0] = o;
        }
        __syncthreads();

        // layer 2: 4k x 8f register tile
        float a2[4][8];
#pragma unroll
        for (int k = 0; k < 4; k++)
#pragma unroll
            for (int j = 0; j < 8; j++) a2[k][j] = 0.f;
#pragma unroll 4
        for (int c = 0; c < 64; c++) {
            float4 hv = *(const float4*)&hb[c * 32 + k0];
            float4 wa = *(const float4*)&w2s[c * 128 + f2];
            float4 wb = *(const float4*)&w2s[c * 128 + f2 + 4];
            float hvv[4] = {hv.x, hv.y, hv.z, hv.w};
            float wvv[8] = {wa.x, wa.y, wa.z, wa.w, wb.x, wb.y, wb.z, wb.w};
#pragma unroll
            for (int k = 0; k < 4; k++)
#pragma unroll
                for (int j = 0; j < 8; j++) a2[k][j] += hvv[k] * wvv[j];
        }

        // bias + relu + max over local 4 k, then max over the 8 kt lanes
        // (consecutive lanes, same ft) via width-8 shfl tree. Exact.
        float m[8];
#pragma unroll
        for (int j = 0; j < 8; j++) {
            float bb = b2s[f2 + j];
            float v = fmaxf(a2[0][j] + bb, 0.f);
            v = fmaxf(v, fmaxf(a2[1][j] + bb, 0.f));
            v = fmaxf(v, fmaxf(a2[2][j] + bb, 0.f));
            v = fmaxf(v, fmaxf(a2[3][j] + bb, 0.f));
            m[j] = v;
        }
#pragma unroll
        for (int off = 4; off > 0; off >>= 1)
#pragma unroll
            for (int j = 0; j < 8; j++)
                m[j] = fmaxf(m[j], __shfl_down_sync(0xffffffffu, m[j], off, 8));
        if (kt == 0) {
            float* op = newpts + (size_t)cid * 128 + f2;
            *(float4*)op       = make_float4(m[0], m[1], m[2], m[3]);
            *(float4*)(op + 4) = make_float4(m[4], m[5], m[6], m[7]);
        }
        __syncthreads();   // protect hb reuse next iteration
    }
}

// ---------------- launch ----------------------------------------------------
extern "C" void kernel_launch(void* const* d_in, const int* in_sizes, int n_in,
                              void* d_out, int out_size) {
    const float* xyz    = (const float*)d_in[0];
    const float* points = (const float*)d_in[1];
    const float* w0     = (const float*)d_in[2];
    const float* b0     = (const float*)d_in[3];
    const float* w1     = (const float*)d_in[4];
    const float* b1     = (const float*)d_in[5];
    const float* w2     = (const float*)d_in[6];
    const float* b2     = (const float*)d_in[7];

    float* newxyz = (float*)d_out;                       // [16,1024,3]
    float* newpts = newxyz + (size_t)BATCH * NPT * 3;    // [16,1024,128]

    cudaFuncSetAttribute(pre_kernel,   cudaFuncAttributeMaxDynamicSharedMemorySize, 49408);
    cudaFuncSetAttribute(query_kernel, cudaFuncAttributeMaxDynamicSharedMemorySize, 49152);
    cudaFuncSetAttribute(mlp_kernel,   cudaFuncAttributeMaxDynamicSharedMemorySize, 67072);

    pre_kernel<<<272, 512, 49408>>>(xyz, points, w0, b0, newxyz);
    query_kernel<<<BATCH * NPT / 8, 256, 49152>>>(newxyz);
    mlp_kernel<<<BATCH * NPT / 4, 256, 67072>>>(xyz, w0, b1, w1, w2, b2, newxyz, newpts);
}